// round 6
// baseline (speedup 1.0000x reference)
#include <cuda_runtime.h>
#include <cuda_bf16.h>
#include <cstdint>

#define BB 8
#define SS 2048
#define EE 1024
#define HH 64
#define NROWS (BB*SS)
#define LDT 72          // padded row stride in bf16 elems for 64-col tiles
#define LDTB (LDT*2)    // 144 bytes

// ---------------- device-global scratch (no allocation allowed) -------------
__device__ unsigned short g_Qhi[NROWS*HH];
__device__ unsigned short g_Qlo[NROWS*HH];
__device__ unsigned short g_Khi[NROWS*HH];
__device__ unsigned short g_Klo[NROWS*HH];
__device__ unsigned short g_Vhi[NROWS*HH];
__device__ unsigned short g_Vlo[NROWS*HH];
__device__ unsigned g_mask_bits[(size_t)BB*SS*(SS/32)];
__device__ int g_mask_mode;   // 0=int32, 1=uint8, 2=float32

// ---------------- base-ISA tensor helpers (sm_80+, no 'a' gating) -----------
__device__ __forceinline__ uint32_t smem_u32(const void* p) {
    uint32_t a;
    asm("{ .reg .u64 t; cvta.to.shared.u64 t, %1; cvt.u32.u64 %0, t; }" : "=r"(a) : "l"(p));
    return a;
}
__device__ __forceinline__ void ldsm4(uint32_t* r, uint32_t a) {
    asm volatile("ldmatrix.sync.aligned.m8n8.x4.shared.b16 {%0,%1,%2,%3}, [%4];"
        : "=r"(r[0]), "=r"(r[1]), "=r"(r[2]), "=r"(r[3]) : "r"(a));
}
__device__ __forceinline__ void ldsm4t(uint32_t* r, uint32_t a) {
    asm volatile("ldmatrix.sync.aligned.m8n8.x4.trans.shared.b16 {%0,%1,%2,%3}, [%4];"
        : "=r"(r[0]), "=r"(r[1]), "=r"(r[2]), "=r"(r[3]) : "r"(a));
}
__device__ __forceinline__ void mma16816(float* c, const uint32_t* a, uint32_t b0, uint32_t b1) {
    asm volatile("mma.sync.aligned.m16n8k16.row.col.f32.bf16.bf16.f32 "
        "{%0,%1,%2,%3}, {%4,%5,%6,%7}, {%8,%9}, {%0,%1,%2,%3};"
        : "+f"(c[0]), "+f"(c[1]), "+f"(c[2]), "+f"(c[3])
        : "r"(a[0]), "r"(a[1]), "r"(a[2]), "r"(a[3]), "r"(b0), "r"(b1));
}
// split x0,x1 into packed bf16x2 hi-word and lo-word (2-term Dekker split)
__device__ __forceinline__ void split2(float x0, float x1, uint32_t& hw, uint32_t& lw) {
    __nv_bfloat16 h0 = __float2bfloat16(x0), h1 = __float2bfloat16(x1);
    float r0 = x0 - __bfloat162float(h0);
    float r1 = x1 - __bfloat162float(h1);
    __nv_bfloat16 l0 = __float2bfloat16(r0), l1 = __float2bfloat16(r1);
    hw = (uint32_t)__bfloat16_as_ushort(h0) | ((uint32_t)__bfloat16_as_ushort(h1) << 16);
    lw = (uint32_t)__bfloat16_as_ushort(l0) | ((uint32_t)__bfloat16_as_ushort(l1) << 16);
}

// ---------------- mask detect + bitpack -------------------------------------
__global__ void detect_mask_kernel(const unsigned int* __restrict__ m) {
    const int lane = threadIdx.x;
    bool all_01 = true, all_f = true;
    for (int i = lane; i < 256; i += 32) {
        unsigned v = m[i];
        if (v > 1u) all_01 = false;
        if (v != 0u && v != 0x3F800000u) all_f = false;
    }
    all_01 = __all_sync(0xFFFFFFFFu, all_01);
    all_f  = __all_sync(0xFFFFFFFFu, all_f);
    if (lane == 0) g_mask_mode = all_01 ? 0 : (all_f ? 2 : 1);
}
__global__ __launch_bounds__(256) void pack_mask_kernel(const void* __restrict__ mask) {
    size_t i = (size_t)blockIdx.x * 256 + threadIdx.x;
    bool mv;
    if (g_mask_mode == 1) mv = ((const unsigned char*)mask)[i] != 0;
    else                  mv = ((const unsigned*)mask)[i] != 0u;
    unsigned w = __ballot_sync(0xFFFFFFFFu, mv);
    if ((threadIdx.x & 31) == 0) g_mask_bits[i >> 5] = w;
}

// ---------------- projection: HMMA bf16x3, 128x64 tile per CTA --------------
// smem: A_hi[128][72], A_lo, W_hi[64][72], W_lo  (bf16, padded rows)
#define PJ_AH 0
#define PJ_AL (PJ_AH + 128*LDTB)
#define PJ_WH (PJ_AL + 128*LDTB)
#define PJ_WL (PJ_WH + 64*LDTB)
#define PJ_SMEM (PJ_WL + 64*LDTB)

__global__ __launch_bounds__(256, 1) void proj_kernel(
    const float* __restrict__ A0, const float* __restrict__ A1, const float* __restrict__ A2,
    const float* __restrict__ W0, const float* __restrict__ W1, const float* __restrict__ W2,
    const float* __restrict__ b0, const float* __restrict__ b1, const float* __restrict__ b2)
{
    extern __shared__ char smem[];
    const uint32_t sb = smem_u32(smem);
    const int tid  = threadIdx.x;
    const int warp = tid >> 5, lane = tid & 31;
    const int quad = lane & 3, qrow = lane >> 2;

    const float *A, *W, *bias; unsigned short *Oh, *Ol;
    if (blockIdx.y == 0)      { A = A0; W = W0; bias = b0; Oh = g_Qhi; Ol = g_Qlo; }
    else if (blockIdx.y == 1) { A = A1; W = W1; bias = b1; Oh = g_Khi; Ol = g_Klo; }
    else                      { A = A2; W = W2; bias = b2; Oh = g_Vhi; Ol = g_Vlo; }
    const int row0 = blockIdx.x * 128;

    float acc[8][4] = {};

    for (int kc = 0; kc < 16; kc++) {
        const int k0 = kc * 64;
        __syncthreads();
        // stage A chunk [128 rows x 64 k] fp32 -> bf16 hi/lo
        #pragma unroll
        for (int i = 0; i < 16; i++) {
            int idx = tid + i * 256;
            int r = idx >> 5, pr = idx & 31;
            float2 x = *(const float2*)(A + (size_t)(row0 + r) * EE + k0 + pr * 2);
            uint32_t hw, lw; split2(x.x, x.y, hw, lw);
            *(uint32_t*)(smem + PJ_AH + r * LDTB + pr * 4) = hw;
            *(uint32_t*)(smem + PJ_AL + r * LDTB + pr * 4) = lw;
        }
        // stage W chunk [64 e x 64 h]
        #pragma unroll
        for (int i = 0; i < 8; i++) {
            int idx = tid + i * 256;
            int k = idx >> 5, np = idx & 31;
            float2 x = *(const float2*)(W + (size_t)(k0 + k) * HH + np * 2);
            uint32_t hw, lw; split2(x.x, x.y, hw, lw);
            *(uint32_t*)(smem + PJ_WH + k * LDTB + np * 4) = hw;
            *(uint32_t*)(smem + PJ_WL + k * LDTB + np * 4) = lw;
        }
        __syncthreads();

        #pragma unroll
        for (int ks = 0; ks < 4; ks++) {
            uint32_t ah[4], al[4];
            uint32_t aaddr = sb + PJ_AH +
                (uint32_t)((16 * warp + (lane & 15)) * LDTB + (ks * 16 + (lane >> 4) * 8) * 2);
            ldsm4(ah, aaddr);
            ldsm4(al, aaddr + (PJ_AL - PJ_AH));
            #pragma unroll
            for (int nbp = 0; nbp < 4; nbp++) {
                uint32_t wh[4], wl[4];
                uint32_t waddr = sb + PJ_WH +
                    (uint32_t)((ks * 16 + (lane & 15)) * LDTB + (nbp * 16 + (lane >> 4) * 8) * 2);
                ldsm4t(wh, waddr);
                ldsm4t(wl, waddr + (PJ_WL - PJ_WH));
                mma16816(acc[2*nbp],   ah, wh[0], wh[1]);
                mma16816(acc[2*nbp],   ah, wl[0], wl[1]);
                mma16816(acc[2*nbp],   al, wh[0], wh[1]);
                mma16816(acc[2*nbp+1], ah, wh[2], wh[3]);
                mma16816(acc[2*nbp+1], ah, wl[2], wl[3]);
                mma16816(acc[2*nbp+1], al, wh[2], wh[3]);
            }
        }
    }

    // epilogue: +bias, split to hi/lo, store
    const int r0g = row0 + 16 * warp + qrow;
    const int r1g = r0g + 8;
    #pragma unroll
    for (int nb = 0; nb < 8; nb++) {
        const int c = 8 * nb + 2 * quad;
        const float bv0 = bias[c], bv1 = bias[c + 1];
        uint32_t h00, l00, h10, l10;
        split2(acc[nb][0] + bv0, acc[nb][1] + bv1, h00, l00);
        split2(acc[nb][2] + bv0, acc[nb][3] + bv1, h10, l10);
        *(uint32_t*)(Oh + (size_t)r0g * HH + c) = h00;
        *(uint32_t*)(Ol + (size_t)r0g * HH + c) = l00;
        *(uint32_t*)(Oh + (size_t)r1g * HH + c) = h10;
        *(uint32_t*)(Ol + (size_t)r1g * HH + c) = l10;
    }
}

// ---------------- attention: HMMA flash, 128-query tile per CTA -------------
// smem: Q_hi, Q_lo, K_hi, K_lo, V_hi, V_lo — each [128][72] bf16
#define AT_Q_H 0
#define AT_Q_L (AT_Q_H + 128*LDTB)
#define AT_K_H (AT_Q_L + 128*LDTB)
#define AT_K_L (AT_K_H + 128*LDTB)
#define AT_V_H (AT_K_L + 128*LDTB)
#define AT_V_L (AT_V_H + 128*LDTB)
#define AT_SMEM (AT_V_L + 128*LDTB)

__global__ __launch_bounds__(256, 1) void attn_kernel(float* __restrict__ Out)
{
    extern __shared__ char smem[];
    const uint32_t sb = smem_u32(smem);
    const int tid  = threadIdx.x;
    const int warp = tid >> 5, lane = tid & 31;
    const int quad = lane & 3, qrow = lane >> 2;
    const int b  = blockIdx.y;
    const int q0 = blockIdx.x * 128;

    // ---- stage Q tile, build resident Q fragments ----
    {
        const unsigned short* qh = g_Qhi + ((size_t)b * SS + q0) * HH;
        const unsigned short* ql = g_Qlo + ((size_t)b * SS + q0) * HH;
        #pragma unroll
        for (int i = 0; i < 4; i++) {
            int idx = tid + i * 256;
            int r = idx >> 3, cg = idx & 7;
            *(uint4*)(smem + AT_Q_H + r * LDTB + cg * 16) = *(const uint4*)(qh + (size_t)r * HH + cg * 8);
            *(uint4*)(smem + AT_Q_L + r * LDTB + cg * 16) = *(const uint4*)(ql + (size_t)r * HH + cg * 8);
        }
    }
    __syncthreads();
    uint32_t qfh[4][4], qfl[4][4];
    #pragma unroll
    for (int ks = 0; ks < 4; ks++) {
        uint32_t aaddr = sb + AT_Q_H +
            (uint32_t)((16 * warp + (lane & 15)) * LDTB + (ks * 16 + (lane >> 4) * 8) * 2);
        ldsm4(qfh[ks], aaddr);
        ldsm4(qfl[ks], aaddr + (AT_Q_L - AT_Q_H));
    }

    const int r0 = 16 * warp + qrow;       // local row in tile
    const int r1 = r0 + 8;
    const unsigned* mrow0 = g_mask_bits + ((size_t)b * SS + q0 + r0) * (SS / 32);
    const unsigned* mrow1 = g_mask_bits + ((size_t)b * SS + q0 + r1) * (SS / 32);

    float O[8][4] = {};
    float m0 = -INFINITY, m1 = -INFINITY, l0 = 0.f, l1 = 0.f;

    for (int kt = 0; kt < 16; kt++) {
        __syncthreads();
        {   // stage K/V tiles (pre-split bf16)
            const size_t base = ((size_t)b * SS + kt * 128) * HH;
            const unsigned short* kh = g_Khi + base;
            const unsigned short* kl = g_Klo + base;
            const unsigned short* vh = g_Vhi + base;
            const unsigned short* vl = g_Vlo + base;
            #pragma unroll
            for (int i = 0; i < 4; i++) {
                int idx = tid + i * 256;
                int r = idx >> 3, cg = idx & 7;
                size_t s = (size_t)r * HH + cg * 8;
                int d = r * LDTB + cg * 16;
                *(uint4*)(smem + AT_K_H + d) = *(const uint4*)(kh + s);
                *(uint4*)(smem + AT_K_L + d) = *(const uint4*)(kl + s);
                *(uint4*)(smem + AT_V_H + d) = *(const uint4*)(vh + s);
                *(uint4*)(smem + AT_V_L + d) = *(const uint4*)(vl + s);
            }
        }
        __syncthreads();

        // ---- S = Q @ K^T : m16 x n128 x k64 per warp, bf16x3 ----
        float c[16][4] = {};
        #pragma unroll
        for (int ks = 0; ks < 4; ks++) {
            #pragma unroll
            for (int nbp = 0; nbp < 8; nbp++) {
                uint32_t kh[4], kl[4];
                uint32_t kaddr = sb + AT_K_H +
                    (uint32_t)((nbp * 16 + (lane & 15)) * LDTB + (ks * 16 + (lane >> 4) * 8) * 2);
                ldsm4(kh, kaddr);
                ldsm4(kl, kaddr + (AT_K_L - AT_K_H));
                mma16816(c[2*nbp],   qfh[ks], kh[0], kh[2]);
                mma16816(c[2*nbp],   qfh[ks], kl[0], kl[2]);
                mma16816(c[2*nbp],   qfl[ks], kh[0], kh[2]);
                mma16816(c[2*nbp+1], qfh[ks], kh[1], kh[3]);
                mma16816(c[2*nbp+1], qfh[ks], kl[1], kl[3]);
                mma16816(c[2*nbp+1], qfl[ks], kh[1], kh[3]);
            }
        }

        // ---- mask + scale, row max (pass 1) ----
        uint4 mq0 = *(const uint4*)(mrow0 + kt * 4);
        uint4 mq1 = *(const uint4*)(mrow1 + kt * 4);
        const unsigned w0a[4] = { mq0.x, mq0.y, mq0.z, mq0.w };
        const unsigned w1a[4] = { mq1.x, mq1.y, mq1.z, mq1.w };
        float lmax0 = -INFINITY, lmax1 = -INFINITY;
        #pragma unroll
        for (int nb = 0; nb < 16; nb++) {
            const unsigned wm0 = w0a[nb >> 2], wm1 = w1a[nb >> 2];
            #pragma unroll
            for (int jj = 0; jj < 2; jj++) {
                const int col = 8 * nb + 2 * quad + jj;
                const int sh = col & 31;
                float s0 = ((wm0 >> sh) & 1u) ? 1e-10f : c[nb][jj]     * 0.125f;
                float s1 = ((wm1 >> sh) & 1u) ? 1e-10f : c[nb][2 + jj] * 0.125f;
                c[nb][jj]     = s0;
                c[nb][2 + jj] = s1;
                lmax0 = fmaxf(lmax0, s0);
                lmax1 = fmaxf(lmax1, s1);
            }
        }
        lmax0 = fmaxf(lmax0, __shfl_xor_sync(0xFFFFFFFFu, lmax0, 1));
        lmax0 = fmaxf(lmax0, __shfl_xor_sync(0xFFFFFFFFu, lmax0, 2));
        lmax1 = fmaxf(lmax1, __shfl_xor_sync(0xFFFFFFFFu, lmax1, 1));
        lmax1 = fmaxf(lmax1, __shfl_xor_sync(0xFFFFFFFFu, lmax1, 2));
        const float mn0 = fmaxf(m0, lmax0), mn1 = fmaxf(m1, lmax1);
        const float al0 = __expf(m0 - mn0), al1 = __expf(m1 - mn1);
        m0 = mn0; m1 = mn1;

        // ---- exp (pass 2), row sums ----
        float ls0 = 0.f, ls1 = 0.f;
        #pragma unroll
        for (int nb = 0; nb < 16; nb++) {
            float p0 = __expf(c[nb][0] - mn0);
            float p1 = __expf(c[nb][1] - mn0);
            float p2 = __expf(c[nb][2] - mn1);
            float p3 = __expf(c[nb][3] - mn1);
            ls0 += p0 + p1; ls1 += p2 + p3;
            c[nb][0] = p0; c[nb][1] = p1; c[nb][2] = p2; c[nb][3] = p3;
        }
        ls0 += __shfl_xor_sync(0xFFFFFFFFu, ls0, 1);
        ls0 += __shfl_xor_sync(0xFFFFFFFFu, ls0, 2);
        ls1 += __shfl_xor_sync(0xFFFFFFFFu, ls1, 1);
        ls1 += __shfl_xor_sync(0xFFFFFFFFu, ls1, 2);
        l0 = l0 * al0 + ls0;
        l1 = l1 * al1 + ls1;

        // ---- rescale O, then O += P @ V (k=128, bf16x3, P from registers) ----
        #pragma unroll
        for (int nb = 0; nb < 8; nb++) {
            O[nb][0] *= al0; O[nb][1] *= al0;
            O[nb][2] *= al1; O[nb][3] *= al1;
        }
        #pragma unroll
        for (int ks = 0; ks < 8; ks++) {
            uint32_t pah[4], pal[4];
            split2(c[2*ks][0],   c[2*ks][1],   pah[0], pal[0]);
            split2(c[2*ks][2],   c[2*ks][3],   pah[1], pal[1]);
            split2(c[2*ks+1][0], c[2*ks+1][1], pah[2], pal[2]);
            split2(c[2*ks+1][2], c[2*ks+1][3], pah[3], pal[3]);
            #pragma unroll
            for (int nbp = 0; nbp < 4; nbp++) {
                uint32_t vh[4], vl[4];
                uint32_t vaddr = sb + AT_V_H +
                    (uint32_t)((ks * 16 + (lane & 15)) * LDTB + (nbp * 16 + (lane >> 4) * 8) * 2);
                ldsm4t(vh, vaddr);
                ldsm4t(vl, vaddr + (AT_V_L - AT_V_H));
                mma16816(O[2*nbp],   pah, vh[0], vh[1]);
                mma16816(O[2*nbp],   pah, vl[0], vl[1]);
                mma16816(O[2*nbp],   pal, vh[0], vh[1]);
                mma16816(O[2*nbp+1], pah, vh[2], vh[3]);
                mma16816(O[2*nbp+1], pah, vl[2], vl[3]);
                mma16816(O[2*nbp+1], pal, vh[2], vh[3]);
            }
        }
    }

    // ---- normalize + write ----
    const float inv0 = 1.f / l0, inv1 = 1.f / l1;
    float* out0 = Out + ((size_t)b * SS + q0 + r0) * HH;
    float* out1 = Out + ((size_t)b * SS + q0 + r1) * HH;
    #pragma unroll
    for (int nb = 0; nb < 8; nb++) {
        const int col = 8 * nb + 2 * quad;
        *(float2*)(out0 + col) = make_float2(O[nb][0] * inv0, O[nb][1] * inv0);
        *(float2*)(out1 + col) = make_float2(O[nb][2] * inv1, O[nb][3] * inv1);
    }
}

// ---------------- launch ------------------------------------------------------
extern "C" void kernel_launch(void* const* d_in, const int* in_sizes, int n_in,
                              void* d_out, int out_size)
{
    const float* iQ = (const float*)d_in[0];
    const float* iK = (const float*)d_in[1];
    const float* iV = (const float*)d_in[2];
    const void*  mask = d_in[3];
    const float* Wq = (const float*)d_in[4];
    const float* bq = (const float*)d_in[5];
    const float* Wk = (const float*)d_in[6];
    const float* bk = (const float*)d_in[7];
    const float* Wv = (const float*)d_in[8];
    const float* bv = (const float*)d_in[9];
    float* out = (float*)d_out;

    cudaFuncSetAttribute(proj_kernel, cudaFuncAttributeMaxDynamicSharedMemorySize, PJ_SMEM);
    cudaFuncSetAttribute(attn_kernel, cudaFuncAttributeMaxDynamicSharedMemorySize, AT_SMEM);

    detect_mask_kernel<<<1, 32>>>((const unsigned int*)mask);
    pack_mask_kernel<<<(int)(((size_t)BB * SS * SS) / 256), 256>>>(mask);

    dim3 pgrid(NROWS / 128, 3);
    proj_kernel<<<pgrid, 256, PJ_SMEM>>>(iQ, iK, iV, Wq, Wk, Wv, bq, bk, bv);

    dim3 agrid(SS / 128, BB);
    attn_kernel<<<agrid, 256, AT_SMEM>>>(out);
}

// round 7
// speedup vs baseline: 1.5932x; 1.5932x over previous
#include <cuda_runtime.h>
#include <cuda_fp16.h>
#include <cstdint>

#define BB 8
#define SS 2048
#define EE 1024
#define HH 64
#define NROWS (BB*SS)
#define LDTB 144

__device__ unsigned short g_Q16[NROWS*HH];
__device__ unsigned short g_K16[NROWS*HH];
__device__ unsigned short g_V16[NROWS*HH];
__device__ unsigned short g_W16[3*EE*HH];
__device__ unsigned g_mask_bits[(size_t)BB*SS*(SS/32)];
__device__ int g_mask_mode;

__device__ __forceinline__ uint32_t smem_u32(const void* p) {
    uint32_t a;
    asm("{ .reg .u64 t; cvta.to.shared.u64 t, %1; cvt.u32.u64 %0, t; }" : "=r"(a) : "l"(p));
    return a;
}
__device__ __forceinline__ void ldsm4(uint32_t* r, uint32_t a) {
    asm volatile("ldmatrix.sync.aligned.m8n8.x4.shared.b16 {%0,%1,%2,%3}, [%4];"
        : "=r"(r[0]), "=r"(r[1]), "=r"(r[2]), "=r"(r[3]) : "r"(a));
}
__device__ __forceinline__ void ldsm4t(uint32_t* r, uint32_t a) {
    asm volatile("ldmatrix.sync.aligned.m8n8.x4.trans.shared.b16 {%0,%1,%2,%3}, [%4];"
        : "=r"(r[0]), "=r"(r[1]), "=r"(r[2]), "=r"(r[3]) : "r"(a));
}
__device__ __forceinline__ void mma16816(float* c, const uint32_t* a, uint32_t b0, uint32_t b1) {
    asm volatile("mma.sync.aligned.m16n8k16.row.col.f32.f16.f16.f32 "
        "{%0,%1,%2,%3}, {%4,%5,%6,%7}, {%8,%9}, {%0,%1,%2,%3};"
        : "+f"(c[0]), "+f"(c[1]), "+f"(c[2]), "+f"(c[3])
        : "r"(a[0]), "r"(a[1]), "r"(a[2]), "r"(a[3]), "r"(b0), "r"(b1));
}
#define CP16(dst, src) \
    asm volatile("cp.async.cg.shared.global [%0], [%1], 16;" :: "r"(dst), "l"(src) : "memory")
#define CP_COMMIT() asm volatile("cp.async.commit_group;" ::: "memory")
#define CP_WAIT(n)  asm volatile("cp.async.wait_group %0;" :: "n"(n) : "memory")

__device__ __forceinline__ uint32_t h2u(float x0, float x1) {
    __half2 h = __floats2half2_rn(x0, x1);
    return *reinterpret_cast<uint32_t*>(&h);
}

// ---------------- prep kernels ----------------
__global__ void detect_mask_kernel(const unsigned int* __restrict__ m) {
    const int lane = threadIdx.x;
    bool a01 = true, af = true;
    for (int i = lane; i < 256; i += 32) {
        unsigned v = m[i];
        if (v > 1u) a01 = false;
        if (v != 0u && v != 0x3F800000u) af = false;
    }
    a01 = __all_sync(0xFFFFFFFFu, a01);
    af  = __all_sync(0xFFFFFFFFu, af);
    if (lane == 0) g_mask_mode = a01 ? 0 : (af ? 2 : 1);
}
__global__ __launch_bounds__(256) void pack_mask_kernel(const void* __restrict__ mask) {
    size_t i = (size_t)blockIdx.x * 256 + threadIdx.x;
    bool mv;
    if (g_mask_mode == 1) mv = ((const unsigned char*)mask)[i] != 0;
    else                  mv = ((const unsigned*)mask)[i] != 0u;
    unsigned w = __ballot_sync(0xFFFFFFFFu, mv);
    if ((threadIdx.x & 31) == 0) g_mask_bits[i >> 5] = w;
}
__global__ __launch_bounds__(256) void conv_w_kernel(
    const float* __restrict__ W0, const float* __restrict__ W1, const float* __restrict__ W2) {
    int idx = blockIdx.x * 256 + threadIdx.x;       // 3*EE*HH / 2 threads, 2 elems each
    int m = idx / (EE * HH / 2);
    int r = idx % (EE * HH / 2);
    const float* W = (m == 0) ? W0 : (m == 1) ? W1 : W2;
    float2 x = *(const float2*)(W + 2 * r);
    *(uint32_t*)(g_W16 + m * EE * HH + 2 * r) = h2u(x.x, x.y);
}

// ---------------- projection: A frags direct from gmem, W via cp.async ------
#define PJ_SMEM (2*64*LDTB)
__global__ __launch_bounds__(256) void proj_kernel(
    const float* __restrict__ A0, const float* __restrict__ A1, const float* __restrict__ A2,
    const float* __restrict__ b0, const float* __restrict__ b1, const float* __restrict__ b2)
{
    extern __shared__ char smem[];
    const uint32_t sb = smem_u32(smem);
    const int tid = threadIdx.x, warp = tid >> 5, lane = tid & 31;
    const int quad = lane & 3, qrow = lane >> 2;
    const int m = blockIdx.y;
    const float* A = (m == 0) ? A0 : (m == 1) ? A1 : A2;
    const float* bias = (m == 0) ? b0 : (m == 1) ? b1 : b2;
    unsigned short* Og = (m == 0) ? g_Q16 : (m == 1) ? g_K16 : g_V16;
    const unsigned short* Wg = g_W16 + m * EE * HH;
    const size_t R0 = (size_t)(blockIdx.x * 128 + 16 * warp + qrow);
    const size_t R1 = R0 + 8;
    const int cb = 2 * quad;

    // cp W chunk kc into stage s
    auto cpW = [&](int kc, int s) {
        const unsigned short* src = Wg + kc * 64 * HH;
        uint32_t dst = sb + (uint32_t)(s * 64 * LDTB);
        #pragma unroll
        for (int i = 0; i < 2; i++) {
            int idx = tid + i * 256;
            int row = idx >> 3, seg = idx & 7;
            CP16(dst + row * LDTB + seg * 16, (const char*)src + row * 128 + seg * 16);
        }
    };
    // load A frags for chunk kc
    auto ldA = [&](int kc, uint32_t af[4][4]) {
        #pragma unroll
        for (int ks = 0; ks < 4; ks++) {
            int k = kc * 64 + ks * 16 + cb;
            float2 f0 = *(const float2*)(A + R0 * EE + k);
            float2 f1 = *(const float2*)(A + R1 * EE + k);
            float2 f2 = *(const float2*)(A + R0 * EE + k + 8);
            float2 f3 = *(const float2*)(A + R1 * EE + k + 8);
            af[ks][0] = h2u(f0.x, f0.y); af[ks][1] = h2u(f1.x, f1.y);
            af[ks][2] = h2u(f2.x, f2.y); af[ks][3] = h2u(f3.x, f3.y);
        }
    };

    float acc[8][4] = {};
    uint32_t af[4][4], afn[4][4];
    cpW(0, 0); CP_COMMIT();
    ldA(0, af);

    for (int kc = 0; kc < 16; kc++) {
        const int s = kc & 1;
        if (kc < 15) { cpW(kc + 1, 1 - s); CP_COMMIT(); CP_WAIT(1); }
        else CP_WAIT(0);
        __syncthreads();
        if (kc < 15) ldA(kc + 1, afn);     // overlap LDG with mma
        const uint32_t wbase = sb + (uint32_t)(s * 64 * LDTB);
        #pragma unroll
        for (int ks = 0; ks < 4; ks++) {
            #pragma unroll
            for (int nbp = 0; nbp < 4; nbp++) {
                uint32_t wh[4];
                ldsm4t(wh, wbase + (uint32_t)((ks * 16 + (lane & 15)) * LDTB + (nbp * 16 + (lane >> 4) * 8) * 2));
                mma16816(acc[2*nbp],   af[ks], wh[0], wh[1]);
                mma16816(acc[2*nbp+1], af[ks], wh[2], wh[3]);
            }
        }
        __syncthreads();
        #pragma unroll
        for (int ks = 0; ks < 4; ks++)
            #pragma unroll
            for (int j = 0; j < 4; j++) af[ks][j] = afn[ks][j];
    }

    #pragma unroll
    for (int nb = 0; nb < 8; nb++) {
        const int c = 8 * nb + 2 * quad;
        const float bv0 = bias[c], bv1 = bias[c + 1];
        *(uint32_t*)(Og + R0 * HH + c) = h2u(acc[nb][0] + bv0, acc[nb][1] + bv1);
        *(uint32_t*)(Og + R1 * HH + c) = h2u(acc[nb][2] + bv0, acc[nb][3] + bv1);
    }
}

// ---------------- attention: fp16 flash, cp.async double-buffered K/V -------
#define AT_Q  0
#define AT_K0 (128*LDTB)
#define AT_V0 (2*128*LDTB)
#define AT_KV (2*128*LDTB)      // stage stride
#define AT_SMEM (5*128*LDTB)    // Q + 2*(K+V) = 92160

__global__ __launch_bounds__(256) void attn_kernel(float* __restrict__ Out)
{
    extern __shared__ char smem[];
    const uint32_t sb = smem_u32(smem);
    const int tid = threadIdx.x, warp = tid >> 5, lane = tid & 31;
    const int quad = lane & 3, qrow = lane >> 2;
    const int b = blockIdx.y, q0 = blockIdx.x * 128;

    auto cpKV = [&](int kt, int s) {
        const size_t base = ((size_t)b * SS + kt * 128) * HH;
        const char* ksrc = (const char*)(g_K16 + base);
        const char* vsrc = (const char*)(g_V16 + base);
        uint32_t kdst = sb + AT_K0 + (uint32_t)(s * AT_KV);
        uint32_t vdst = sb + AT_V0 + (uint32_t)(s * AT_KV);
        #pragma unroll
        for (int i = 0; i < 4; i++) {
            int idx = tid + i * 256;
            int row = idx >> 3, seg = idx & 7;
            CP16(kdst + row * LDTB + seg * 16, ksrc + row * 128 + seg * 16);
            CP16(vdst + row * LDTB + seg * 16, vsrc + row * 128 + seg * 16);
        }
    };
    {   // Q + first KV stage in one group
        const char* qsrc = (const char*)(g_Q16 + ((size_t)b * SS + q0) * HH);
        #pragma unroll
        for (int i = 0; i < 4; i++) {
            int idx = tid + i * 256;
            int row = idx >> 3, seg = idx & 7;
            CP16(sb + AT_Q + row * LDTB + seg * 16, qsrc + row * 128 + seg * 16);
        }
        cpKV(0, 0); CP_COMMIT();
    }
    CP_WAIT(0);
    __syncthreads();

    uint32_t qf[4][4];
    #pragma unroll
    for (int ks = 0; ks < 4; ks++)
        ldsm4(qf[ks], sb + AT_Q + (uint32_t)((16 * warp + (lane & 15)) * LDTB + (ks * 16 + (lane >> 4) * 8) * 2));

    const int r0 = 16 * warp + qrow, r1 = r0 + 8;
    const unsigned* mrow0 = g_mask_bits + ((size_t)b * SS + q0 + r0) * (SS / 32);
    const unsigned* mrow1 = g_mask_bits + ((size_t)b * SS + q0 + r1) * (SS / 32);

    float O[8][4] = {};
    float m0 = -INFINITY, m1 = -INFINITY, l0 = 0.f, l1 = 0.f;

    for (int kt = 0; kt < 16; kt++) {
        const int s = kt & 1;
        if (kt < 15) { cpKV(kt + 1, 1 - s); CP_COMMIT(); CP_WAIT(1); }
        else CP_WAIT(0);
        __syncthreads();
        const uint32_t kb = sb + AT_K0 + (uint32_t)(s * AT_KV);
        const uint32_t vb = sb + AT_V0 + (uint32_t)(s * AT_KV);

        // S = Q @ K^T
        float c[16][4] = {};
        #pragma unroll
        for (int ks = 0; ks < 4; ks++) {
            #pragma unroll
            for (int nbp = 0; nbp < 8; nbp++) {
                uint32_t kh[4];
                ldsm4(kh, kb + (uint32_t)((nbp * 16 + (lane & 15)) * LDTB + (ks * 16 + (lane >> 4) * 8) * 2));
                mma16816(c[2*nbp],   qf[ks], kh[0], kh[2]);
                mma16816(c[2*nbp+1], qf[ks], kh[1], kh[3]);
            }
        }

        // mask + scale + row max
        uint4 mq0 = *(const uint4*)(mrow0 + kt * 4);
        uint4 mq1 = *(const uint4*)(mrow1 + kt * 4);
        const unsigned w0a[4] = { mq0.x, mq0.y, mq0.z, mq0.w };
        const unsigned w1a[4] = { mq1.x, mq1.y, mq1.z, mq1.w };
        float x0 = -INFINITY, x1 = -INFINITY;
        #pragma unroll
        for (int nb = 0; nb < 16; nb++) {
            const unsigned wm0 = w0a[nb >> 2], wm1 = w1a[nb >> 2];
            #pragma unroll
            for (int jj = 0; jj < 2; jj++) {
                const int sh = (8 * nb + 2 * quad + jj) & 31;
                float s0 = ((wm0 >> sh) & 1u) ? 1e-10f : c[nb][jj]     * 0.125f;
                float s1 = ((wm1 >> sh) & 1u) ? 1e-10f : c[nb][2 + jj] * 0.125f;
                c[nb][jj] = s0; c[nb][2 + jj] = s1;
                x0 = fmaxf(x0, s0); x1 = fmaxf(x1, s1);
            }
        }
        x0 = fmaxf(x0, __shfl_xor_sync(0xFFFFFFFFu, x0, 1));
        x0 = fmaxf(x0, __shfl_xor_sync(0xFFFFFFFFu, x0, 2));
        x1 = fmaxf(x1, __shfl_xor_sync(0xFFFFFFFFu, x1, 1));
        x1 = fmaxf(x1, __shfl_xor_sync(0xFFFFFFFFu, x1, 2));
        const float mn0 = fmaxf(m0, x0), mn1 = fmaxf(m1, x1);
        const float al0 = __expf(m0 - mn0), al1 = __expf(m1 - mn1);
        m0 = mn0; m1 = mn1;

        float ls0 = 0.f, ls1 = 0.f;
        #pragma unroll
        for (int nb = 0; nb < 16; nb++) {
            float p0 = __expf(c[nb][0] - mn0);
            float p1 = __expf(c[nb][1] - mn0);
            float p2 = __expf(c[nb][2] - mn1);
            float p3 = __expf(c[nb][3] - mn1);
            ls0 += p0 + p1; ls1 += p2 + p3;
            c[nb][0] = p0; c[nb][1] = p1; c[nb][2] = p2; c[nb][3] = p3;
        }
        ls0 += __shfl_xor_sync(0xFFFFFFFFu, ls0, 1);
        ls0 += __shfl_xor_sync(0xFFFFFFFFu, ls0, 2);
        ls1 += __shfl_xor_sync(0xFFFFFFFFu, ls1, 1);
        ls1 += __shfl_xor_sync(0xFFFFFFFFu, ls1, 2);
        l0 = l0 * al0 + ls0;
        l1 = l1 * al1 + ls1;

        #pragma unroll
        for (int nb = 0; nb < 8; nb++) {
            O[nb][0] *= al0; O[nb][1] *= al0;
            O[nb][2] *= al1; O[nb][3] *= al1;
        }
        // O += P @ V
        #pragma unroll
        for (int ks = 0; ks < 8; ks++) {
            uint32_t pa[4];
            pa[0] = h2u(c[2*ks][0],   c[2*ks][1]);
            pa[1] = h2u(c[2*ks][2],   c[2*ks][3]);
            pa[2] = h2u(c[2*ks+1][0], c[2*ks+1][1]);
            pa[3] = h2u(c[2*ks+1][2], c[2*ks+1][3]);
            #pragma unroll
            for (int nbp = 0; nbp < 4; nbp++) {
                uint32_t vh[4];
                ldsm4t(vh, vb + (uint32_t)((ks * 16 + (lane & 15)) * LDTB + (nbp * 16 + (lane >> 4) * 8) * 2));
                mma16816(O[2*nbp],   pa, vh[0], vh[1]);
                mma16816(O[2*nbp+1], pa, vh[2], vh[3]);
            }
        }
        __syncthreads();
    }

    const float inv0 = 1.f / l0, inv1 = 1.f / l1;
    float* out0 = Out + ((size_t)b * SS + q0 + r0) * HH;
    float* out1 = Out + ((size_t)b * SS + q0 + r1) * HH;
    #pragma unroll
    for (int nb = 0; nb < 8; nb++) {
        const int col = 8 * nb + 2 * quad;
        *(float2*)(out0 + col) = make_float2(O[nb][0] * inv0, O[nb][1] * inv0);
        *(float2*)(out1 + col) = make_float2(O[nb][2] * inv1, O[nb][3] * inv1);
    }
}

// ---------------- launch ----------------
extern "C" void kernel_launch(void* const* d_in, const int* in_sizes, int n_in,
                              void* d_out, int out_size)
{
    const float* iQ = (const float*)d_in[0];
    const float* iK = (const float*)d_in[1];
    const float* iV = (const float*)d_in[2];
    const void*  mask = d_in[3];
    const float* Wq = (const float*)d_in[4];
    const float* bq = (const float*)d_in[5];
    const float* Wk = (const float*)d_in[6];
    const float* bk = (const float*)d_in[7];
    const float* Wv = (const float*)d_in[8];
    const float* bv = (const float*)d_in[9];
    float* out = (float*)d_out;

    cudaFuncSetAttribute(attn_kernel, cudaFuncAttributeMaxDynamicSharedMemorySize, AT_SMEM);

    detect_mask_kernel<<<1, 32>>>((const unsigned int*)mask);
    pack_mask_kernel<<<(int)(((size_t)BB * SS * SS) / 256), 256>>>(mask);
    conv_w_kernel<<<3 * EE * HH / 512, 256>>>(Wq, Wk, Wv);

    dim3 pgrid(NROWS / 128, 3);
    proj_kernel<<<pgrid, 256, PJ_SMEM>>>(iQ, iK, iV, bq, bk, bv);

    dim3 agrid(SS / 128, BB);
    attn_kernel<<<agrid, 256, AT_SMEM>>>(out);
}

// round 9
// speedup vs baseline: 2.4001x; 1.5065x over previous
#include <cuda_runtime.h>
#include <cuda_fp16.h>
#include <cstdint>

#define BB 8
#define SS 2048
#define EE 1024
#define HH 64
#define NROWS (BB*SS)

__device__ unsigned short g_Q16[NROWS*HH];
__device__ unsigned short g_K16[NROWS*HH];
__device__ unsigned short g_V16[NROWS*HH];
__device__ unsigned short g_W16[3*EE*HH];
__device__ unsigned g_mask_bits[(size_t)BB*SS*(SS/32)];
__device__ int g_mask_mode;

__device__ __forceinline__ uint32_t smem_u32(const void* p) {
    uint32_t a;
    asm("{ .reg .u64 t; cvta.to.shared.u64 t, %1; cvt.u32.u64 %0, t; }" : "=r"(a) : "l"(p));
    return a;
}
__device__ __forceinline__ void ldsm4(uint32_t* r, uint32_t a) {
    asm volatile("ldmatrix.sync.aligned.m8n8.x4.shared.b16 {%0,%1,%2,%3}, [%4];"
        : "=r"(r[0]), "=r"(r[1]), "=r"(r[2]), "=r"(r[3]) : "r"(a));
}
__device__ __forceinline__ void ldsm4t(uint32_t* r, uint32_t a) {
    asm volatile("ldmatrix.sync.aligned.m8n8.x4.trans.shared.b16 {%0,%1,%2,%3}, [%4];"
        : "=r"(r[0]), "=r"(r[1]), "=r"(r[2]), "=r"(r[3]) : "r"(a));
}
__device__ __forceinline__ void mma16816(float* c, const uint32_t* a, uint32_t b0, uint32_t b1) {
    asm volatile("mma.sync.aligned.m16n8k16.row.col.f32.f16.f16.f32 "
        "{%0,%1,%2,%3}, {%4,%5,%6,%7}, {%8,%9}, {%0,%1,%2,%3};"
        : "+f"(c[0]), "+f"(c[1]), "+f"(c[2]), "+f"(c[3])
        : "r"(a[0]), "r"(a[1]), "r"(a[2]), "r"(a[3]), "r"(b0), "r"(b1));
}
#define CP16(dst, src) \
    asm volatile("cp.async.cg.shared.global [%0], [%1], 16;" :: "r"(dst), "l"(src) : "memory")
#define CP_COMMIT() asm volatile("cp.async.commit_group;" ::: "memory")
#define CP_WAIT(n)  asm volatile("cp.async.wait_group %0;" :: "n"(n) : "memory")

__device__ __forceinline__ uint32_t h2u(float x0, float x1) {
    __half2 h = __floats2half2_rn(x0, x1);
    return *reinterpret_cast<uint32_t*>(&h);
}

// ---------------- prep kernels ----------------
__global__ void detect_mask_kernel(const unsigned int* __restrict__ m) {
    const int lane = threadIdx.x;
    bool a01 = true, af = true;
    for (int i = lane; i < 256; i += 32) {
        unsigned v = m[i];
        if (v > 1u) a01 = false;
        if (v != 0u && v != 0x3F800000u) af = false;
    }
    a01 = __all_sync(0xFFFFFFFFu, a01);
    af  = __all_sync(0xFFFFFFFFu, af);
    if (lane == 0) g_mask_mode = a01 ? 0 : (af ? 2 : 1);
}
// 4 elements per thread; shfl nibble-pack into 32-bit words
__global__ __launch_bounds__(256) void pack_mask_kernel(const void* __restrict__ mask) {
    const unsigned gid = blockIdx.x * 256 + threadIdx.x;
    const int lane = threadIdx.x & 31;
    unsigned nib;
    if (g_mask_mode == 1) {
        unsigned w = ((const unsigned*)mask)[gid];       // 4 bool bytes
        nib = ((w & 0xFFu) ? 1u : 0u) | ((w & 0xFF00u) ? 2u : 0u)
            | ((w & 0xFF0000u) ? 4u : 0u) | ((w & 0xFF000000u) ? 8u : 0u);
    } else {
        uint4 v = ((const uint4*)mask)[gid];             // int32 {0,1} or float {0,1.0f}
        nib = (v.x ? 1u : 0u) | (v.y ? 2u : 0u) | (v.z ? 4u : 0u) | (v.w ? 8u : 0u);
    }
    unsigned u = nib | (__shfl_down_sync(0xFFFFFFFFu, nib, 1) << 4);
    u |= __shfl_down_sync(0xFFFFFFFFu, u, 2) << 8;
    u |= __shfl_down_sync(0xFFFFFFFFu, u, 4) << 16;
    if ((lane & 7) == 0) g_mask_bits[gid >> 3] = u;
}
__global__ __launch_bounds__(256) void conv_w_kernel(
    const float* __restrict__ W0, const float* __restrict__ W1, const float* __restrict__ W2) {
    int idx = blockIdx.x * 256 + threadIdx.x;
    int m = idx / (EE * HH / 2);
    int r = idx % (EE * HH / 2);
    const float* W = (m == 0) ? W0 : (m == 1) ? W1 : W2;
    float2 x = *(const float2*)(W + 2 * r);
    *(uint32_t*)(g_W16 + m * EE * HH + 2 * r) = h2u(x.x, x.y);
}

// ---------------- projection: fp32 A via cp.async, convert in regs ----------
// smem: A fp32 2 stages [128][72 floats] (288B rows), W fp16 2 stages [64][144B]
#define PJA_OFF 0
#define PJW_OFF (2*128*288)                 // 73728
#define PJ_SMEM (PJW_OFF + 2*64*144)        // 92160

__global__ __launch_bounds__(256, 2) void proj_kernel(
    const float* __restrict__ A0, const float* __restrict__ A1, const float* __restrict__ A2,
    const float* __restrict__ b0, const float* __restrict__ b1, const float* __restrict__ b2)
{
    extern __shared__ char smem[];
    const uint32_t sb = smem_u32(smem);
    const int tid = threadIdx.x, warp = tid >> 5, lane = tid & 31;
    const int quad = lane & 3, qrow = lane >> 2;
    const int m = blockIdx.y;
    const float* A = (m == 0) ? A0 : (m == 1) ? A1 : A2;
    const float* bias = (m == 0) ? b0 : (m == 1) ? b1 : b2;
    unsigned short* Og = (m == 0) ? g_Q16 : (m == 1) ? g_K16 : g_V16;
    const unsigned short* Wg = g_W16 + m * EE * HH;
    const int row0 = blockIdx.x * 128;

    auto cpA = [&](int kc, int s) {
        uint32_t dst = sb + PJA_OFF + (uint32_t)(s * 128 * 288);
        #pragma unroll
        for (int i = 0; i < 8; i++) {
            int idx = tid + i * 256;
            int row = idx >> 4, seg = idx & 15;
            CP16(dst + row * 288 + seg * 16,
                 (const char*)(A + (size_t)(row0 + row) * EE + kc * 64) + seg * 16);
        }
    };
    auto cpW = [&](int kc, int s) {
        const char* src = (const char*)(Wg + kc * 64 * HH);
        uint32_t dst = sb + PJW_OFF + (uint32_t)(s * 64 * 144);
        #pragma unroll
        for (int i = 0; i < 2; i++) {
            int idx = tid + i * 256;
            int row = idx >> 3, seg = idx & 7;
            CP16(dst + row * 144 + seg * 16, src + row * 128 + seg * 16);
        }
    };

    float acc[8][4] = {};
    cpA(0, 0); cpW(0, 0); CP_COMMIT();

    const int lr0 = 16 * warp + qrow, lr1 = lr0 + 8;

    for (int kc = 0; kc < 16; kc++) {
        const int s = kc & 1;
        if (kc < 15) { cpA(kc + 1, 1 - s); cpW(kc + 1, 1 - s); CP_COMMIT(); CP_WAIT(1); }
        else CP_WAIT(0);
        __syncthreads();

        const float* As = (const float*)(smem + PJA_OFF + (size_t)s * 128 * 288);
        uint32_t af[4][4];
        #pragma unroll
        for (int ks = 0; ks < 4; ks++) {
            const int k = ks * 16 + 2 * quad;
            float2 f0 = *(const float2*)(As + lr0 * 72 + k);
            float2 f1 = *(const float2*)(As + lr1 * 72 + k);
            float2 f2 = *(const float2*)(As + lr0 * 72 + k + 8);
            float2 f3 = *(const float2*)(As + lr1 * 72 + k + 8);
            af[ks][0] = h2u(f0.x, f0.y); af[ks][1] = h2u(f1.x, f1.y);
            af[ks][2] = h2u(f2.x, f2.y); af[ks][3] = h2u(f3.x, f3.y);
        }
        const uint32_t wbase = sb + PJW_OFF + (uint32_t)(s * 64 * 144);
        #pragma unroll
        for (int ks = 0; ks < 4; ks++) {
            #pragma unroll
            for (int nbp = 0; nbp < 4; nbp++) {
                uint32_t wf[4];
                ldsm4t(wf, wbase + (uint32_t)((ks * 16 + (lane & 15)) * 144 + (nbp * 16 + (lane >> 4) * 8) * 2));
                mma16816(acc[2*nbp],   af[ks], wf[0], wf[1]);
                mma16816(acc[2*nbp+1], af[ks], wf[2], wf[3]);
            }
        }
        __syncthreads();
    }

    const size_t R0 = (size_t)row0 + lr0, R1 = R0 + 8;
    #pragma unroll
    for (int nb = 0; nb < 8; nb++) {
        const int c = 8 * nb + 2 * quad;
        const float bv0 = bias[c], bv1 = bias[c + 1];
        *(uint32_t*)(Og + R0 * HH + c) = h2u(acc[nb][0] + bv0, acc[nb][1] + bv1);
        *(uint32_t*)(Og + R1 * HH + c) = h2u(acc[nb][2] + bv0, acc[nb][3] + bv1);
    }
}

// ---------------- attention: 64-q tiles, warp-pair key split, 2 CTAs/SM -----
// smem: Q [64][144], K 2 stages [128][144], V 2 stages [128][144], red/sum
#define AQ_OFF 0
#define AK_OFF (64*144)                      // 9216
#define AV_OFF (AK_OFF + 2*128*144)          // 46080
#define ARED   (AV_OFF + 2*128*144)          // 82944
#define ASUM   (ARED + 128*4)                // 83456
#define AT_SMEM (ASUM + 128*4)               // 83968

__global__ __launch_bounds__(256, 2) void attn_kernel(float* __restrict__ Out)
{
    extern __shared__ char smem[];
    const uint32_t sb = smem_u32(smem);
    const int tid = threadIdx.x, warp = tid >> 5, lane = tid & 31;
    const int quad = lane & 3, qrow = lane >> 2;
    const int pair = warp >> 1, kh = warp & 1;   // 4 row-pairs x 2 key-halves
    const int b = blockIdx.y, q0 = blockIdx.x * 64;

    float* redmax = (float*)(smem + ARED);
    float* redsum = (float*)(smem + ASUM);

    auto cpKV = [&](int kt, int s) {
        const size_t base = ((size_t)b * SS + kt * 128) * HH;
        const char* ksrc = (const char*)(g_K16 + base);
        const char* vsrc = (const char*)(g_V16 + base);
        uint32_t kdst = sb + AK_OFF + (uint32_t)(s * 128 * 144);
        uint32_t vdst = sb + AV_OFF + (uint32_t)(s * 128 * 144);
        #pragma unroll
        for (int i = 0; i < 4; i++) {
            int idx = tid + i * 256;
            int row = idx >> 3, seg = idx & 7;
            CP16(kdst + row * 144 + seg * 16, ksrc + row * 128 + seg * 16);
            CP16(vdst + row * 144 + seg * 16, vsrc + row * 128 + seg * 16);
        }
    };
    {   // Q (64 rows) + first KV stage in one group
        const char* qsrc = (const char*)(g_Q16 + ((size_t)b * SS + q0) * HH);
        #pragma unroll
        for (int i = 0; i < 2; i++) {
            int idx = tid + i * 256;
            int row = idx >> 3, seg = idx & 7;
            CP16(sb + AQ_OFF + row * 144 + seg * 16, qsrc + row * 128 + seg * 16);
        }
        cpKV(0, 0); CP_COMMIT();
    }
    CP_WAIT(0);
    __syncthreads();

    uint32_t qf[4][4];
    #pragma unroll
    for (int ks = 0; ks < 4; ks++)
        ldsm4(qf[ks], sb + AQ_OFF + (uint32_t)((16 * pair + (lane & 15)) * 144 + (ks * 16 + (lane >> 4) * 8) * 2));

    const int r0 = 16 * pair + qrow, r1 = r0 + 8;    // rows in 64-row tile
    const unsigned* mrow0 = g_mask_bits + ((size_t)b * SS + q0 + r0) * (SS / 32);
    const unsigned* mrow1 = g_mask_bits + ((size_t)b * SS + q0 + r1) * (SS / 32);

    float O[8][4] = {};
    float m0 = -INFINITY, m1 = -INFINITY, l0 = 0.f, l1 = 0.f;

    for (int kt = 0; kt < 16; kt++) {
        const int s = kt & 1;
        if (kt < 15) { cpKV(kt + 1, 1 - s); CP_COMMIT(); CP_WAIT(1); }
        else CP_WAIT(0);
        __syncthreads();
        const uint32_t kb = sb + AK_OFF + (uint32_t)(s * 128 * 144);
        const uint32_t vb = sb + AV_OFF + (uint32_t)(s * 128 * 144);

        // S = Q @ K^T for this warp's 64-key half
        float c[8][4] = {};
        #pragma unroll
        for (int ks = 0; ks < 4; ks++) {
            #pragma unroll
            for (int nbp = 0; nbp < 4; nbp++) {
                uint32_t kf[4];
                ldsm4(kf, kb + (uint32_t)((kh * 64 + nbp * 16 + (lane & 15)) * 144 + (ks * 16 + (lane >> 4) * 8) * 2));
                mma16816(c[2*nbp],   qf[ks], kf[0], kf[2]);
                mma16816(c[2*nbp+1], qf[ks], kf[1], kf[3]);
            }
        }

        // mask + scale + local max over 64 cols
        uint2 mw0 = *(const uint2*)(mrow0 + kt * 4 + kh * 2);
        uint2 mw1 = *(const uint2*)(mrow1 + kt * 4 + kh * 2);
        float x0 = -INFINITY, x1 = -INFINITY;
        #pragma unroll
        for (int nb = 0; nb < 8; nb++) {
            #pragma unroll
            for (int jj = 0; jj < 2; jj++) {
                const int cw = 8 * nb + 2 * quad + jj;
                const unsigned w0 = (cw < 32) ? mw0.x : mw0.y;
                const unsigned w1 = (cw < 32) ? mw1.x : mw1.y;
                const int sh = cw & 31;
                float s0 = ((w0 >> sh) & 1u) ? 1e-10f : c[nb][jj]     * 0.125f;
                float s1 = ((w1 >> sh) & 1u) ? 1e-10f : c[nb][2 + jj] * 0.125f;
                c[nb][jj] = s0; c[nb][2 + jj] = s1;
                x0 = fmaxf(x0, s0); x1 = fmaxf(x1, s1);
            }
        }
        x0 = fmaxf(x0, __shfl_xor_sync(0xFFFFFFFFu, x0, 1));
        x0 = fmaxf(x0, __shfl_xor_sync(0xFFFFFFFFu, x0, 2));
        x1 = fmaxf(x1, __shfl_xor_sync(0xFFFFFFFFu, x1, 1));
        x1 = fmaxf(x1, __shfl_xor_sync(0xFFFFFFFFu, x1, 2));
        if (quad == 0) { redmax[kh * 64 + r0] = x0; redmax[kh * 64 + r1] = x1; }
        __syncthreads();
        const float mn0 = fmaxf(m0, fmaxf(redmax[r0], redmax[64 + r0]));
        const float mn1 = fmaxf(m1, fmaxf(redmax[r1], redmax[64 + r1]));
        const float al0 = __expf(m0 - mn0), al1 = __expf(m1 - mn1);
        m0 = mn0; m1 = mn1;

        float ls0 = 0.f, ls1 = 0.f;
        #pragma unroll
        for (int nb = 0; nb < 8; nb++) {
            float p0 = __expf(c[nb][0] - mn0);
            float p1 = __expf(c[nb][1] - mn0);
            float p2 = __expf(c[nb][2] - mn1);
            float p3 = __expf(c[nb][3] - mn1);
            ls0 += p0 + p1; ls1 += p2 + p3;
            c[nb][0] = p0; c[nb][1] = p1; c[nb][2] = p2; c[nb][3] = p3;
        }
        ls0 += __shfl_xor_sync(0xFFFFFFFFu, ls0, 1);
        ls0 += __shfl_xor_sync(0xFFFFFFFFu, ls0, 2);
        ls1 += __shfl_xor_sync(0xFFFFFFFFu, ls1, 1);
        ls1 += __shfl_xor_sync(0xFFFFFFFFu, ls1, 2);
        if (quad == 0) { redsum[kh * 64 + r0] = ls0; redsum[kh * 64 + r1] = ls1; }
        __syncthreads();
        l0 = l0 * al0 + redsum[r0] + redsum[64 + r0];
        l1 = l1 * al1 + redsum[r1] + redsum[64 + r1];

        #pragma unroll
        for (int nb = 0; nb < 8; nb++) {
            O[nb][0] *= al0; O[nb][1] *= al0;
            O[nb][2] *= al1; O[nb][3] *= al1;
        }
        // O += P @ V over this warp's 64 keys
        #pragma unroll
        for (int ks = 0; ks < 4; ks++) {
            uint32_t pa[4];
            pa[0] = h2u(c[2*ks][0],   c[2*ks][1]);
            pa[1] = h2u(c[2*ks][2],   c[2*ks][3]);
            pa[2] = h2u(c[2*ks+1][0], c[2*ks+1][1]);
            pa[3] = h2u(c[2*ks+1][2], c[2*ks+1][3]);
            #pragma unroll
            for (int nbp = 0; nbp < 4; nbp++) {
                uint32_t vf[4];
                ldsm4t(vf, vb + (uint32_t)((kh * 64 + ks * 16 + (lane & 15)) * 144 + (nbp * 16 + (lane >> 4) * 8) * 2));
                mma16816(O[2*nbp],   pa, vf[0], vf[1]);
                mma16816(O[2*nbp+1], pa, vf[2], vf[3]);
            }
        }
        // REQUIRED: all warps must finish reading stage s before any warp's
        // next-iteration cp.async prefetch overwrites it (round-8 race fix).
        __syncthreads();
    }

    // pair-sum O halves via smem (reuse K region), normalize, write
    float* xb = (float*)(smem + AK_OFF);   // [64 rows][72 floats]
    if (kh == 1) {
        #pragma unroll
        for (int nb = 0; nb < 8; nb++) {
            const int col = 8 * nb + 2 * quad;
            xb[r0 * 72 + col]     = O[nb][0];
            xb[r0 * 72 + col + 1] = O[nb][1];
            xb[r1 * 72 + col]     = O[nb][2];
            xb[r1 * 72 + col + 1] = O[nb][3];
        }
    }
    __syncthreads();
    if (kh == 0) {
        const float inv0 = 1.f / l0, inv1 = 1.f / l1;
        float* out0 = Out + ((size_t)b * SS + q0 + r0) * HH;
        float* out1 = Out + ((size_t)b * SS + q0 + r1) * HH;
        #pragma unroll
        for (int nb = 0; nb < 8; nb++) {
            const int col = 8 * nb + 2 * quad;
            *(float2*)(out0 + col) = make_float2((O[nb][0] + xb[r0 * 72 + col])     * inv0,
                                                 (O[nb][1] + xb[r0 * 72 + col + 1]) * inv0);
            *(float2*)(out1 + col) = make_float2((O[nb][2] + xb[r1 * 72 + col])     * inv1,
                                                 (O[nb][3] + xb[r1 * 72 + col + 1]) * inv1);
        }
    }
}

// ---------------- launch ----------------
extern "C" void kernel_launch(void* const* d_in, const int* in_sizes, int n_in,
                              void* d_out, int out_size)
{
    const float* iQ = (const float*)d_in[0];
    const float* iK = (const float*)d_in[1];
    const float* iV = (const float*)d_in[2];
    const void*  mask = d_in[3];
    const float* Wq = (const float*)d_in[4];
    const float* bq = (const float*)d_in[5];
    const float* Wk = (const float*)d_in[6];
    const float* bk = (const float*)d_in[7];
    const float* Wv = (const float*)d_in[8];
    const float* bv = (const float*)d_in[9];
    float* out = (float*)d_out;

    cudaFuncSetAttribute(proj_kernel, cudaFuncAttributeMaxDynamicSharedMemorySize, PJ_SMEM);
    cudaFuncSetAttribute(attn_kernel, cudaFuncAttributeMaxDynamicSharedMemorySize, AT_SMEM);

    detect_mask_kernel<<<1, 32>>>((const unsigned int*)mask);
    pack_mask_kernel<<<(int)(((size_t)BB * SS * SS) / 1024), 256>>>(mask);
    conv_w_kernel<<<3 * EE * HH / 512, 256>>>(Wq, Wk, Wv);

    dim3 pgrid(NROWS / 128, 3);
    proj_kernel<<<pgrid, 256, PJ_SMEM>>>(iQ, iK, iV, bq, bk, bv);

    dim3 agrid(SS / 64, BB);
    attn_kernel<<<agrid, 256, AT_SMEM>>>(out);
}